// round 14
// baseline (speedup 1.0000x reference)
#include <cuda_runtime.h>
#include <cuda_fp16.h>
#include <cstdint>

#define D_DIM 128
#define MAX_N 200064
#define MAX_K 512

__device__ float g_sums[MAX_K * D_DIM];
__device__ int   g_counts[MAX_K];
__device__ int   g_assign[MAX_N];
__device__ float g_c2[MAX_K];
__device__ float g_f2[MAX_N];
__device__ uint32_t g_Ctf[MAX_K * D_DIM];   // tf32 of centers (bit patterns)

__device__ __forceinline__ uint32_t f2tf32(float x) {
    uint32_t r; asm("cvt.rna.tf32.f32 %0, %1;" : "=r"(r) : "f"(x)); return r;
}
__device__ __forceinline__ void mma_tf32(float* d, const uint32_t* a,
                                         uint32_t b0, uint32_t b1) {
    asm volatile(
        "mma.sync.aligned.m16n8k8.row.col.f32.tf32.tf32.f32 "
        "{%0,%1,%2,%3}, {%4,%5,%6,%7}, {%8,%9}, {%0,%1,%2,%3};"
        : "+f"(d[0]), "+f"(d[1]), "+f"(d[2]), "+f"(d[3])
        : "r"(a[0]), "r"(a[1]), "r"(a[2]), "r"(a[3]), "r"(b0), "r"(b1));
}

// ---------------------------------------------------------------------------
// Fused prep: zero sums/counts, tf32-convert C, f2, c2.
// ---------------------------------------------------------------------------
__global__ void prep_kernel(const float* __restrict__ F,
                            const float* __restrict__ C, int N, int K) {
    const int t = blockIdx.x * blockDim.x + threadIdx.x;
    const int KD = K * D_DIM;
    if (t < KD) {
        g_sums[t] = 0.0f;
        g_Ctf[t] = f2tf32(C[t]);
    }
    if (t < K) g_counts[t] = 0;

    const int w = t >> 5;
    const int lane = t & 31;
    if (w < N) {
        float4 v = reinterpret_cast<const float4*>(F + (size_t)w * D_DIM)[lane];
        float s = v.x * v.x + v.y * v.y + v.z * v.z + v.w * v.w;
        #pragma unroll
        for (int o = 16; o > 0; o >>= 1) s += __shfl_xor_sync(0xffffffffu, s, o);
        if (lane == 0) g_f2[w] = s;
    } else if (w < N + K) {
        int k = w - N;
        float4 v = reinterpret_cast<const float4*>(C + (size_t)k * D_DIM)[lane];
        float s = v.x * v.x + v.y * v.y + v.z * v.z + v.w * v.w;
        #pragma unroll
        for (int o = 16; o > 0; o >>= 1) s += __shfl_xor_sync(0xffffffffu, s, o);
        if (lane == 0) g_c2[k] = s;
    }
}

// ---------------------------------------------------------------------------
// 1-pass tf32 mma + exact fp32 rescore of near-best candidates.
//   Block: 256 thr / 8 warps (4 M x 2 N). Tile: 128 points x ALL 512 centers.
//   sA (64KB): F tile tf32, fragment-staged (validated layout from R13).
//   sB (2x8KB): C chunk (128 centers x 16 d), double-buffered, frag-staged.
//   sS (133KB): fp16 approx scores [128 pts][pitch 520].
//   Phase B: threads 0..127 scan own point's 512 scores; rescore candidates
//   within EPS of approx best exactly in fp32; argmin (first-min tie-break).
// ---------------------------------------------------------------------------
#define SPITCH_H 520
#define OFF_A 0
#define OFF_B 65536
#define OFF_S 81920
#define OFF_R (OFF_S + 128 * SPITCH_H * 2)        // 2x128 floats
#define SMEM_TOTAL (OFF_R + 1024)
#define EPS 1.0f

__global__ __launch_bounds__(256, 1) void assign_kernel(
    const float* __restrict__ F, const float* __restrict__ Cf, int N, int K)
{
    extern __shared__ char smem[];
    uint32_t* sA = reinterpret_cast<uint32_t*>(smem + OFF_A);
    uint32_t* sB = reinterpret_cast<uint32_t*>(smem + OFF_B);
    __half*   sS = reinterpret_cast<__half*>(smem + OFF_S);
    float*    sBv = reinterpret_cast<float*>(smem + OFF_R);

    const int tid  = threadIdx.x;
    const int wid  = tid >> 5;
    const int lane = tid & 31;
    const int mw = wid & 3;
    const int nw = wid >> 2;
    const int g  = lane >> 2;
    const int q  = lane & 3;
    const int p0 = blockIdx.x * 128;

    // ---- stage F tile into sA (tf32, fragment order; convert once) ----
    {
        int row = tid >> 1;
        int prow = p0 + row; if (prow >= N) prow = N - 1;
        const int dbase = (tid & 1) * 64;
        const float4* src = reinterpret_cast<const float4*>(
            F + (size_t)prow * D_DIM + dbase);
        const int mwmt = row >> 4;
        const int rbit = (row >> 3) & 1;
        const int lrow4 = (row & 7) * 4;
        #pragma unroll
        for (int j = 0; j < 16; ++j) {
            float4 v = src[j];
            float vv[4] = { v.x, v.y, v.z, v.w };
            #pragma unroll
            for (int e = 0; e < 4; ++e) {
                int d = dbase + j * 4 + e;
                int ks = d >> 3;
                int r  = ((d >> 2) & 1) * 2 + rbit;
                int ln = lrow4 + (d & 3);
                sA[((mwmt * 16 + ks) * 32 + ln) * 4 + r] = f2tf32(vv[e]);
            }
        }
    }

    float D[2][8][4];
    #pragma unroll
    for (int mt = 0; mt < 2; mt++)
        #pragma unroll
        for (int n = 0; n < 8; n++)
            #pragma unroll
            for (int e = 0; e < 4; e++) D[mt][n][e] = 0.0f;

    float bestv[4]; float f2v[4];
    #pragma unroll
    for (int s = 0; s < 4; s++) {
        bestv[s] = __int_as_float(0x7f800000);
        int row = p0 + mw * 32 + (s >> 1) * 16 + g + 8 * (s & 1);
        if (row >= N) row = N - 1;
        f2v[s] = g_f2[row];
    }

    // ---- B loader (thread: center lc = tid>>1, 8 d's at ldh) ----
    const int lc   = tid >> 1;
    const int ldh  = (tid & 1) * 8;
    const int lg4  = (lc & 7) * 4;
    const int bslot = ((lc >> 3)) * 128;      // (lnw*8+lnn)*128 floats

    const int nkt = K >> 7;                    // 4 k-tiles
    const int it_total = nkt * 8;

    uint4 h0, h1;
    {
        size_t base = (size_t)lc * D_DIM + ldh;
        h0 = *reinterpret_cast<const uint4*>(g_Ctf + base);
        h1 = *reinterpret_cast<const uint4*>(g_Ctf + base + 4);
    }
    {
        uint32_t* dst = sB;
        uint32_t hv[8] = { h0.x,h0.y,h0.z,h0.w, h1.x,h1.y,h1.z,h1.w };
        #pragma unroll
        for (int j = 0; j < 8; ++j) {
            int dd = ldh + j;
            dst[bslot + (lg4 + (dd & 3)) * 4 + (dd >> 3) * 2 + ((dd >> 2) & 1)] = hv[j];
        }
    }
    __syncthreads();

    for (int it = 0; it < it_total; ++it) {
        const int kt = it >> 3;
        const int dc = it & 7;
        const int cur = it & 1;
        const bool more = (it + 1 < it_total);

        if (more) {
            int nit = it + 1;
            size_t base = (size_t)(((nit >> 3) * 128) + lc) * D_DIM + (nit & 7) * 16 + ldh;
            h0 = *reinterpret_cast<const uint4*>(g_Ctf + base);
            h1 = *reinterpret_cast<const uint4*>(g_Ctf + base + 4);
        }

        // A fragments: 4 x LDS.128
        const int ks0 = dc * 2;
        uint4 ah[2][2];
        #pragma unroll
        for (int mt = 0; mt < 2; ++mt)
            #pragma unroll
            for (int kk = 0; kk < 2; ++kk)
                ah[mt][kk] = *reinterpret_cast<const uint4*>(
                    sA + (((mw * 2 + mt) * 16 + (ks0 + kk)) * 32 + lane) * 4);

        const uint32_t* bbuf = sB + cur * 2048;
        #pragma unroll
        for (int n = 0; n < 8; ++n) {
            uint4 bh = *reinterpret_cast<const uint4*>(
                bbuf + ((nw * 8 + n) * 32 + lane) * 4);
            #pragma unroll
            for (int mt = 0; mt < 2; ++mt) {
                mma_tf32(D[mt][n], reinterpret_cast<const uint32_t*>(&ah[mt][0]), bh.x, bh.y);
                mma_tf32(D[mt][n], reinterpret_cast<const uint32_t*>(&ah[mt][1]), bh.z, bh.w);
            }
        }

        if (more) {
            uint32_t* dst = sB + (cur ^ 1) * 2048;
            uint32_t hv[8] = { h0.x,h0.y,h0.z,h0.w, h1.x,h1.y,h1.z,h1.w };
            #pragma unroll
            for (int j = 0; j < 8; ++j) {
                int dd = ldh + j;
                dst[bslot + (lg4 + (dd & 3)) * 4 + (dd >> 3) * 2 + ((dd >> 2) & 1)] = hv[j];
            }
        }
        __syncthreads();

        // ---- k-tile boundary: approx scores -> sS (fp16) + bestv ----
        if (dc == 7) {
            #pragma unroll
            for (int n = 0; n < 8; ++n) {
                const int cb = kt * 128 + nw * 64 + n * 8 + 2 * q;
                const float c2a = g_c2[cb];
                const float c2b = g_c2[cb + 1];
                #pragma unroll
                for (int mt = 0; mt < 2; ++mt)
                    #pragma unroll
                    for (int h = 0; h < 2; ++h) {
                        const int s = mt * 2 + h;
                        const int row = mw * 32 + mt * 16 + g + 8 * h;
                        float sa = (f2v[s] - 2.0f * D[mt][n][h * 2 + 0]) + c2a;
                        float sb = (f2v[s] - 2.0f * D[mt][n][h * 2 + 1]) + c2b;
                        sS[row * SPITCH_H + cb]     = __float2half_rn(sa);
                        sS[row * SPITCH_H + cb + 1] = __float2half_rn(sb);
                        if (sa < bestv[s]) bestv[s] = sa;
                        if (sb < bestv[s]) bestv[s] = sb;
                        D[mt][n][h * 2 + 0] = 0.0f;
                        D[mt][n][h * 2 + 1] = 0.0f;
                    }
            }
        }
    }
    __syncthreads();

    // ---- reduce approx best across quad lanes, publish per (nw,row) ----
    #pragma unroll
    for (int s = 0; s < 4; ++s) {
        float v = bestv[s];
        #pragma unroll
        for (int off = 1; off < 4; off <<= 1) {
            float ov = __shfl_down_sync(0xffffffffu, v, off, 4);
            if (ov < v) v = ov;
        }
        if (q == 0) {
            int row = mw * 32 + (s >> 1) * 16 + g + 8 * (s & 1);
            sBv[nw * 128 + row] = v;
        }
    }
    __syncthreads();

    // ---- phase B: exact fp32 rescore of candidates ----
    if (tid < 128) {
        const int p = tid;
        int prow = p0 + p; if (prow >= N) prow = N - 1;
        const float th = fminf(sBv[p], sBv[128 + p]) + EPS;
        const float f2p = g_f2[prow];
        const float4* Frow4 = reinterpret_cast<const float4*>(F + (size_t)prow * D_DIM);
        const __half* srow = sS + p * SPITCH_H;

        float best = __int_as_float(0x7f800000);
        int   bi = 0;
        for (int k = 0; k < K; ++k) {
            float h = __half2float(srow[k]);
            if (h <= th) {
                const float4* Crow4 = reinterpret_cast<const float4*>(Cf + (size_t)k * D_DIM);
                float dot = 0.0f;
                #pragma unroll
                for (int j = 0; j < 32; ++j) {
                    float4 a = Frow4[j];
                    float4 b = Crow4[j];
                    dot = fmaf(a.x, b.x, dot);
                    dot = fmaf(a.y, b.y, dot);
                    dot = fmaf(a.z, b.z, dot);
                    dot = fmaf(a.w, b.w, dot);
                }
                float sc = (f2p - 2.0f * dot) + g_c2[k];
                if (sc < best) { best = sc; bi = k; }
            }
        }
        if (p0 + p < N) g_assign[p0 + p] = bi;
    }
}

// ---------------------------------------------------------------------------
__global__ void seg_kernel(const float* __restrict__ F, int N) {
    int w = (blockIdx.x * blockDim.x + threadIdx.x) >> 5;
    int lane = threadIdx.x & 31;
    if (w >= N) return;
    int a = g_assign[w];
    float4 v = reinterpret_cast<const float4*>(F + (size_t)w * D_DIM)[lane];
    float* dst = g_sums + (size_t)a * D_DIM + lane * 4;
    asm volatile("red.global.add.v4.f32 [%0], {%1, %2, %3, %4};"
                 :: "l"(dst), "f"(v.x), "f"(v.y), "f"(v.z), "f"(v.w)
                 : "memory");
    if (lane == 0) atomicAdd(&g_counts[a], 1);
}

__global__ void final_kernel(float* __restrict__ out, int KD, int nAssign) {
    int i = blockIdx.x * blockDim.x + threadIdx.x;
    if (i < KD) {
        float c = (float)g_counts[i / D_DIM];
        out[i] = g_sums[i] / fmaxf(c, 1.0f);
    } else {
        int a = i - KD;
        if (a < nAssign) out[KD + a] = (float)g_assign[a];
    }
}

// ---------------------------------------------------------------------------
extern "C" void kernel_launch(void* const* d_in, const int* in_sizes, int n_in,
                              void* d_out, int out_size)
{
    (void)n_in;
    const float* F = (const float*)d_in[0];
    const float* C = (const float*)d_in[1];
    const int D = D_DIM;
    const int N = in_sizes[0] / D;
    const int K = in_sizes[1] / D;
    float* out = (float*)d_out;
    const int KD = K * D;

    cudaFuncSetAttribute(assign_kernel,
                         cudaFuncAttributeMaxDynamicSharedMemorySize, SMEM_TOTAL);

    const int prepThreads = (N + K) * 32;
    prep_kernel<<<(prepThreads + 255) / 256, 256>>>(F, C, N, K);
    assign_kernel<<<(N + 127) / 128, 256, SMEM_TOTAL>>>(F, C, N, K);
    seg_kernel<<<(N + 7) / 8, 256>>>(F, N);

    int centersPart, assignPart;
    if (out_size >= KD + N)      { centersPart = KD; assignPart = N; }
    else if (out_size >= KD)     { centersPart = KD; assignPart = out_size - KD; }
    else                         { centersPart = 0;  assignPart = out_size; }
    int total = centersPart + assignPart;
    if (total > 0)
        final_kernel<<<(total + 255) / 256, 256>>>(out, centersPart, assignPart);
}

// round 15
// speedup vs baseline: 1.1734x; 1.1734x over previous
#include <cuda_runtime.h>
#include <cuda_fp16.h>
#include <cstdint>

#define D_DIM 128
#define MAX_N 200064
#define MAX_K 512

__device__ float g_sums[MAX_K * D_DIM];
__device__ int   g_counts[MAX_K];
__device__ int   g_assign[MAX_N];
__device__ float g_c2[MAX_K];
__device__ float g_f2[MAX_N];
__device__ uint32_t g_Ctf[MAX_K * D_DIM];        // tf32 of centers
__device__ __half g_scores[(size_t)MAX_N * MAX_K];  // approx scores (205MB scratch)

__device__ __forceinline__ uint32_t f2tf32(float x) {
    uint32_t r; asm("cvt.rna.tf32.f32 %0, %1;" : "=r"(r) : "f"(x)); return r;
}
__device__ __forceinline__ void mma_tf32(float* d, const uint32_t* a,
                                         uint32_t b0, uint32_t b1) {
    asm volatile(
        "mma.sync.aligned.m16n8k8.row.col.f32.tf32.tf32.f32 "
        "{%0,%1,%2,%3}, {%4,%5,%6,%7}, {%8,%9}, {%0,%1,%2,%3};"
        : "+f"(d[0]), "+f"(d[1]), "+f"(d[2]), "+f"(d[3])
        : "r"(a[0]), "r"(a[1]), "r"(a[2]), "r"(a[3]), "r"(b0), "r"(b1));
}

// ---------------------------------------------------------------------------
// Fused prep: zero sums/counts, tf32-convert C, f2, c2.
// ---------------------------------------------------------------------------
__global__ void prep_kernel(const float* __restrict__ F,
                            const float* __restrict__ C, int N, int K) {
    const int t = blockIdx.x * blockDim.x + threadIdx.x;
    const int KD = K * D_DIM;
    if (t < KD) {
        g_sums[t] = 0.0f;
        g_Ctf[t] = f2tf32(C[t]);
    }
    if (t < K) g_counts[t] = 0;

    const int w = t >> 5;
    const int lane = t & 31;
    if (w < N) {
        float4 v = reinterpret_cast<const float4*>(F + (size_t)w * D_DIM)[lane];
        float s = v.x * v.x + v.y * v.y + v.z * v.z + v.w * v.w;
        #pragma unroll
        for (int o = 16; o > 0; o >>= 1) s += __shfl_xor_sync(0xffffffffu, s, o);
        if (lane == 0) g_f2[w] = s;
    } else if (w < N + K) {
        int k = w - N;
        float4 v = reinterpret_cast<const float4*>(C + (size_t)k * D_DIM)[lane];
        float s = v.x * v.x + v.y * v.y + v.z * v.z + v.w * v.w;
        #pragma unroll
        for (int o = 16; o > 0; o >>= 1) s += __shfl_xor_sync(0xffffffffu, s, o);
        if (lane == 0) g_c2[k] = s;
    }
}

// ---------------------------------------------------------------------------
// 1-pass tf32 mma; approx scores written to g_scores (fp16).
//   Block: 256 thr / 8 warps (4 M x 2 N). Tile: 128 points x 512 centers.
//   sA (64KB): F tile tf32, fragment-staged (layout validated in R13/R14).
//   sB (2x8KB): C chunk (128 centers x 16 d), double-buffered, frag-staged.
//   smem total 80KB -> 2 CTAs/SM.
// ---------------------------------------------------------------------------
#define OFF_A 0
#define OFF_B 65536
#define SMEM_TOTAL (65536 + 16384)
#define EPS 1.0f

__global__ __launch_bounds__(256, 2) void assign_kernel(
    const float* __restrict__ F, int N, int K)
{
    extern __shared__ char smem[];
    uint32_t* sA = reinterpret_cast<uint32_t*>(smem + OFF_A);
    uint32_t* sB = reinterpret_cast<uint32_t*>(smem + OFF_B);

    const int tid  = threadIdx.x;
    const int wid  = tid >> 5;
    const int lane = tid & 31;
    const int mw = wid & 3;
    const int nw = wid >> 2;
    const int g  = lane >> 2;
    const int q  = lane & 3;
    const int p0 = blockIdx.x * 128;

    // ---- stage F tile into sA (tf32, fragment order; convert once) ----
    {
        int row = tid >> 1;
        int prow = p0 + row; if (prow >= N) prow = N - 1;
        const int dbase = (tid & 1) * 64;
        const float4* src = reinterpret_cast<const float4*>(
            F + (size_t)prow * D_DIM + dbase);
        const int mwmt = row >> 4;
        const int rbit = (row >> 3) & 1;
        const int lrow4 = (row & 7) * 4;
        #pragma unroll
        for (int j = 0; j < 16; ++j) {
            float4 v = src[j];
            float vv[4] = { v.x, v.y, v.z, v.w };
            #pragma unroll
            for (int e = 0; e < 4; ++e) {
                int d = dbase + j * 4 + e;
                int ks = d >> 3;
                int r  = ((d >> 2) & 1) * 2 + rbit;
                int ln = lrow4 + (d & 3);
                sA[((mwmt * 16 + ks) * 32 + ln) * 4 + r] = f2tf32(vv[e]);
            }
        }
    }

    float D[2][8][4];
    #pragma unroll
    for (int mt = 0; mt < 2; mt++)
        #pragma unroll
        for (int n = 0; n < 8; n++)
            #pragma unroll
            for (int e = 0; e < 4; e++) D[mt][n][e] = 0.0f;

    float f2v[4];
    #pragma unroll
    for (int s = 0; s < 4; s++) {
        int row = p0 + mw * 32 + (s >> 1) * 16 + g + 8 * (s & 1);
        if (row >= N) row = N - 1;
        f2v[s] = g_f2[row];
    }

    // ---- B loader (thread: center lc = tid>>1, 8 d's at ldh) ----
    const int lc   = tid >> 1;
    const int ldh  = (tid & 1) * 8;
    const int lg4  = (lc & 7) * 4;
    const int bslot = (lc >> 3) * 128;

    const int nkt = K >> 7;
    const int it_total = nkt * 8;

    uint4 h0, h1;
    {
        size_t base = (size_t)lc * D_DIM + ldh;
        h0 = *reinterpret_cast<const uint4*>(g_Ctf + base);
        h1 = *reinterpret_cast<const uint4*>(g_Ctf + base + 4);
    }
    {
        uint32_t* dst = sB;
        uint32_t hv[8] = { h0.x,h0.y,h0.z,h0.w, h1.x,h1.y,h1.z,h1.w };
        #pragma unroll
        for (int j = 0; j < 8; ++j) {
            int dd = ldh + j;
            dst[bslot + (lg4 + (dd & 3)) * 4 + (dd >> 3) * 2 + ((dd >> 2) & 1)] = hv[j];
        }
    }
    __syncthreads();

    for (int it = 0; it < it_total; ++it) {
        const int kt = it >> 3;
        const int dc = it & 7;
        const int cur = it & 1;
        const bool more = (it + 1 < it_total);

        if (more) {
            int nit = it + 1;
            size_t base = (size_t)(((nit >> 3) * 128) + lc) * D_DIM + (nit & 7) * 16 + ldh;
            h0 = *reinterpret_cast<const uint4*>(g_Ctf + base);
            h1 = *reinterpret_cast<const uint4*>(g_Ctf + base + 4);
        }

        // A fragments: 4 x LDS.128
        const int ks0 = dc * 2;
        uint4 ah[2][2];
        #pragma unroll
        for (int mt = 0; mt < 2; ++mt)
            #pragma unroll
            for (int kk = 0; kk < 2; ++kk)
                ah[mt][kk] = *reinterpret_cast<const uint4*>(
                    sA + (((mw * 2 + mt) * 16 + (ks0 + kk)) * 32 + lane) * 4);

        const uint32_t* bbuf = sB + cur * 2048;
        #pragma unroll
        for (int n = 0; n < 8; ++n) {
            uint4 bh = *reinterpret_cast<const uint4*>(
                bbuf + ((nw * 8 + n) * 32 + lane) * 4);
            #pragma unroll
            for (int mt = 0; mt < 2; ++mt) {
                mma_tf32(D[mt][n], reinterpret_cast<const uint32_t*>(&ah[mt][0]), bh.x, bh.y);
                mma_tf32(D[mt][n], reinterpret_cast<const uint32_t*>(&ah[mt][1]), bh.z, bh.w);
            }
        }

        if (more) {
            uint32_t* dst = sB + (cur ^ 1) * 2048;
            uint32_t hv[8] = { h0.x,h0.y,h0.z,h0.w, h1.x,h1.y,h1.z,h1.w };
            #pragma unroll
            for (int j = 0; j < 8; ++j) {
                int dd = ldh + j;
                dst[bslot + (lg4 + (dd & 3)) * 4 + (dd >> 3) * 2 + ((dd >> 2) & 1)] = hv[j];
            }
        }
        __syncthreads();

        // ---- k-tile boundary: approx scores -> g_scores (fp16x2) ----
        if (dc == 7) {
            #pragma unroll
            for (int n = 0; n < 8; ++n) {
                const int cb = kt * 128 + nw * 64 + n * 8 + 2 * q;
                const float c2a = g_c2[cb];
                const float c2b = g_c2[cb + 1];
                #pragma unroll
                for (int mt = 0; mt < 2; ++mt)
                    #pragma unroll
                    for (int h = 0; h < 2; ++h) {
                        const int s = mt * 2 + h;
                        const int row = mw * 32 + mt * 16 + g + 8 * h;
                        const int p = p0 + row;
                        float sa = (f2v[s] - 2.0f * D[mt][n][h * 2 + 0]) + c2a;
                        float sb = (f2v[s] - 2.0f * D[mt][n][h * 2 + 1]) + c2b;
                        if (p < N) {
                            __half2 hv2 = __floats2half2_rn(sa, sb);
                            *reinterpret_cast<__half2*>(
                                g_scores + (size_t)p * MAX_K + cb) = hv2;
                        }
                        D[mt][n][h * 2 + 0] = 0.0f;
                        D[mt][n][h * 2 + 1] = 0.0f;
                    }
            }
        }
    }
}

// ---------------------------------------------------------------------------
// Rescore: one warp per point. Coalesced score-row read, warp min, exact fp32
// rescore of all candidates within EPS (guaranteed to contain true argmin).
// ---------------------------------------------------------------------------
__global__ void rescore_kernel(const float* __restrict__ F,
                               const float* __restrict__ Cf, int N, int K)
{
    const int w = (blockIdx.x * blockDim.x + threadIdx.x) >> 5;
    const int lane = threadIdx.x & 31;
    if (w >= N) return;

    const uint4* srow = reinterpret_cast<const uint4*>(g_scores + (size_t)w * MAX_K);
    uint4 s0 = srow[lane];
    uint4 s1 = srow[32 + lane];
    uint32_t u[8] = { s0.x, s0.y, s0.z, s0.w, s1.x, s1.y, s1.z, s1.w };
    float v[16];
    #pragma unroll
    for (int jw = 0; jw < 8; ++jw) {
        __half2 h2 = *reinterpret_cast<__half2*>(&u[jw]);
        v[2 * jw]     = __low2float(h2);
        v[2 * jw + 1] = __high2float(h2);
    }

    float mn = v[0];
    #pragma unroll
    for (int j = 1; j < 16; ++j) mn = fminf(mn, v[j]);
    #pragma unroll
    for (int off = 16; off > 0; off >>= 1)
        mn = fminf(mn, __shfl_xor_sync(0xffffffffu, mn, off));
    const float th = mn + EPS;

    const float f2p = g_f2[w];
    const float4* Fr = reinterpret_cast<const float4*>(F + (size_t)w * D_DIM);

    float best = __int_as_float(0x7f800000);
    int   bi = K;
    #pragma unroll
    for (int j = 0; j < 16; ++j) {
        if (v[j] <= th) {
            int k = (j < 8) ? (lane * 8 + j) : (256 + lane * 8 + (j - 8));
            const float4* Cr = reinterpret_cast<const float4*>(Cf + (size_t)k * D_DIM);
            float dot = 0.0f;
            #pragma unroll
            for (int t = 0; t < 32; ++t) {
                float4 a = Fr[t];
                float4 b = Cr[t];
                dot = fmaf(a.x, b.x, dot);
                dot = fmaf(a.y, b.y, dot);
                dot = fmaf(a.z, b.z, dot);
                dot = fmaf(a.w, b.w, dot);
            }
            float sc = (f2p - 2.0f * dot) + g_c2[k];
            if (sc < best || (sc == best && k < bi)) { best = sc; bi = k; }
        }
    }

    #pragma unroll
    for (int off = 16; off > 0; off >>= 1) {
        float ov = __shfl_down_sync(0xffffffffu, best, off);
        int   oi = __shfl_down_sync(0xffffffffu, bi, off);
        if (ov < best || (ov == best && oi < bi)) { best = ov; bi = oi; }
    }
    if (lane == 0) g_assign[w] = bi;
}

// ---------------------------------------------------------------------------
__global__ void seg_kernel(const float* __restrict__ F, int N) {
    int w = (blockIdx.x * blockDim.x + threadIdx.x) >> 5;
    int lane = threadIdx.x & 31;
    if (w >= N) return;
    int a = g_assign[w];
    float4 v = reinterpret_cast<const float4*>(F + (size_t)w * D_DIM)[lane];
    float* dst = g_sums + (size_t)a * D_DIM + lane * 4;
    asm volatile("red.global.add.v4.f32 [%0], {%1, %2, %3, %4};"
                 :: "l"(dst), "f"(v.x), "f"(v.y), "f"(v.z), "f"(v.w)
                 : "memory");
    if (lane == 0) atomicAdd(&g_counts[a], 1);
}

__global__ void final_kernel(float* __restrict__ out, int KD, int nAssign) {
    int i = blockIdx.x * blockDim.x + threadIdx.x;
    if (i < KD) {
        float c = (float)g_counts[i / D_DIM];
        out[i] = g_sums[i] / fmaxf(c, 1.0f);
    } else {
        int a = i - KD;
        if (a < nAssign) out[KD + a] = (float)g_assign[a];
    }
}

// ---------------------------------------------------------------------------
extern "C" void kernel_launch(void* const* d_in, const int* in_sizes, int n_in,
                              void* d_out, int out_size)
{
    (void)n_in;
    const float* F = (const float*)d_in[0];
    const float* C = (const float*)d_in[1];
    const int D = D_DIM;
    const int N = in_sizes[0] / D;
    const int K = in_sizes[1] / D;
    float* out = (float*)d_out;
    const int KD = K * D;

    cudaFuncSetAttribute(assign_kernel,
                         cudaFuncAttributeMaxDynamicSharedMemorySize, SMEM_TOTAL);

    const int prepThreads = (N + K) * 32;
    prep_kernel<<<(prepThreads + 255) / 256, 256>>>(F, C, N, K);
    assign_kernel<<<(N + 127) / 128, 256, SMEM_TOTAL>>>(F, N, K);
    rescore_kernel<<<(N + 7) / 8, 256>>>(F, C, N, K);
    seg_kernel<<<(N + 7) / 8, 256>>>(F, N);

    int centersPart, assignPart;
    if (out_size >= KD + N)      { centersPart = KD; assignPart = N; }
    else if (out_size >= KD)     { centersPart = KD; assignPart = out_size - KD; }
    else                         { centersPart = 0;  assignPart = out_size; }
    int total = centersPart + assignPart;
    if (total > 0)
        final_kernel<<<(total + 255) / 256, 256>>>(out, centersPart, assignPart);
}